// round 10
// baseline (speedup 1.0000x reference)
#include <cuda_runtime.h>

// Problem constants
#define Bc 4
#define Lc 512
#define Dc 768
#define Wc 12
#define Mrows   (Bc * Lc)          // 2048
#define Mout    (Bc * Lc * Wc)     // 24576
#define Kproj   Dc                 // 768
#define Nproj   (2 * Dc)           // 1536
#define Kout    (3 * Dc)           // 2304
#define Nout    Dc                 // 768

// GEMM tiling
#define BM 128
#define BN 128
#define BKK 8
#define TM 8
#define TN 8
#define NTHREADS 256

// Scratch (device globals; allocation is forbidden)
__device__ float g_proj[Mrows * Nproj];          // 12.6 MB  [b*L+l][e]
__device__ float g_conv[(size_t)Mout * Dc];      // 75.5 MB  [((b*L+l)*W+k)][o]
__device__ float g_cw[Wc * Dc * Dc];             // 28.3 MB  [k][o][c]

// ---------------------------------------------------------------------------
// Pack conv_w (o, c, k) -> (k, o, c) for coalesced GEMM-B loads
// ---------------------------------------------------------------------------
__global__ void pack_convw(const float* __restrict__ cw) {
    int i = blockIdx.x * blockDim.x + threadIdx.x;
    if (i >= Wc * Dc * Dc) return;
    int c = i % Dc;
    int t = i / Dc;
    int o = t % Dc;
    int k = t / Dc;
    g_cw[i] = cw[(o * Dc + c) * Wc + k];
}

// ---------------------------------------------------------------------------
// GEMM 1: proj[m, e] = sum_d h[m, d] * proj_w[e, d] + proj_b[e]
//   M=2048, N=1536, K=768
// ---------------------------------------------------------------------------
__global__ __launch_bounds__(NTHREADS)
void gemm_proj(const float* __restrict__ A, const float* __restrict__ Bw,
               const float* __restrict__ bias) {
    __shared__ float As[BKK][BM];
    __shared__ float Bs[BKK][BN];
    const int K = Kproj, N = Nproj;
    int bm = blockIdx.y * BM, bn = blockIdx.x * BN;
    int t = threadIdx.x;
    int lr = t >> 1, lc4 = (t & 1) * 4;
    int ty = t >> 4, tx = t & 15;

    float acc[TM][TN];
#pragma unroll
    for (int i = 0; i < TM; i++)
#pragma unroll
        for (int j = 0; j < TN; j++) acc[i][j] = 0.f;

    for (int k0 = 0; k0 < K; k0 += BKK) {
        float4 av = *(const float4*)(A + (size_t)(bm + lr) * K + k0 + lc4);
        As[lc4 + 0][lr] = av.x; As[lc4 + 1][lr] = av.y;
        As[lc4 + 2][lr] = av.z; As[lc4 + 3][lr] = av.w;
        float4 bv = *(const float4*)(Bw + (size_t)(bn + lr) * K + k0 + lc4);
        Bs[lc4 + 0][lr] = bv.x; Bs[lc4 + 1][lr] = bv.y;
        Bs[lc4 + 2][lr] = bv.z; Bs[lc4 + 3][lr] = bv.w;
        __syncthreads();
#pragma unroll
        for (int kk = 0; kk < BKK; kk++) {
            float ar[TM], br[TN];
#pragma unroll
            for (int i = 0; i < TM; i++) ar[i] = As[kk][ty * TM + i];
#pragma unroll
            for (int j = 0; j < TN; j++) br[j] = Bs[kk][tx * TN + j];
#pragma unroll
            for (int i = 0; i < TM; i++)
#pragma unroll
                for (int j = 0; j < TN; j++) acc[i][j] += ar[i] * br[j];
        }
        __syncthreads();
    }

    float bvv[TN];
#pragma unroll
    for (int j = 0; j < TN; j++) bvv[j] = bias[bn + tx * TN + j];
#pragma unroll
    for (int i = 0; i < TM; i++) {
        int gm = bm + ty * TM + i;
        float4 v0, v1;
        v0.x = acc[i][0] + bvv[0]; v0.y = acc[i][1] + bvv[1];
        v0.z = acc[i][2] + bvv[2]; v0.w = acc[i][3] + bvv[3];
        v1.x = acc[i][4] + bvv[4]; v1.y = acc[i][5] + bvv[5];
        v1.z = acc[i][6] + bvv[6]; v1.w = acc[i][7] + bvv[7];
        *(float4*)(g_proj + (size_t)gm * N + bn + tx * TN)     = v0;
        *(float4*)(g_proj + (size_t)gm * N + bn + tx * TN + 4) = v1;
    }
}

// ---------------------------------------------------------------------------
// GEMM 2: P[m, o; k] = sum_c h[b, l+k, c] * g_cw[k][o][c]   (0 if l+k >= L)
//   grid.z = k. M=2048, N=768, K=768. Output indexed [m*W + k][o].
// ---------------------------------------------------------------------------
__global__ __launch_bounds__(NTHREADS)
void gemm_conv(const float* __restrict__ h) {
    __shared__ float As[BKK][BM];
    __shared__ float Bs[BKK][BN];
    const int K = Dc, N = Dc;
    int kz = blockIdx.z;
    int bm = blockIdx.y * BM, bn = blockIdx.x * BN;
    int t = threadIdx.x;
    int lr = t >> 1, lc4 = (t & 1) * 4;
    int ty = t >> 4, tx = t & 15;

    // per-thread A row (constant over k-loop)
    int m = bm + lr;
    int b = m >> 9;           // /512
    int l = m & 511;
    int ls = l + kz;
    const float* arow = (ls < Lc) ? (h + ((size_t)(b * Lc + ls)) * Dc) : nullptr;
    const float* brow = g_cw + (size_t)kz * Dc * Dc + (size_t)(bn + lr) * K;

    float acc[TM][TN];
#pragma unroll
    for (int i = 0; i < TM; i++)
#pragma unroll
        for (int j = 0; j < TN; j++) acc[i][j] = 0.f;

    for (int k0 = 0; k0 < K; k0 += BKK) {
        float4 av = make_float4(0.f, 0.f, 0.f, 0.f);
        if (arow) av = *(const float4*)(arow + k0 + lc4);
        As[lc4 + 0][lr] = av.x; As[lc4 + 1][lr] = av.y;
        As[lc4 + 2][lr] = av.z; As[lc4 + 3][lr] = av.w;
        float4 bv = *(const float4*)(brow + k0 + lc4);
        Bs[lc4 + 0][lr] = bv.x; Bs[lc4 + 1][lr] = bv.y;
        Bs[lc4 + 2][lr] = bv.z; Bs[lc4 + 3][lr] = bv.w;
        __syncthreads();
#pragma unroll
        for (int kk = 0; kk < BKK; kk++) {
            float ar[TM], br[TN];
#pragma unroll
            for (int i = 0; i < TM; i++) ar[i] = As[kk][ty * TM + i];
#pragma unroll
            for (int j = 0; j < TN; j++) br[j] = Bs[kk][tx * TN + j];
#pragma unroll
            for (int i = 0; i < TM; i++)
#pragma unroll
                for (int j = 0; j < TN; j++) acc[i][j] += ar[i] * br[j];
        }
        __syncthreads();
    }

#pragma unroll
    for (int i = 0; i < TM; i++) {
        int gm = bm + ty * TM + i;
        size_t base = ((size_t)gm * Wc + kz) * (size_t)N + bn + tx * TN;
        float4 v0, v1;
        v0.x = acc[i][0]; v0.y = acc[i][1]; v0.z = acc[i][2]; v0.w = acc[i][3];
        v1.x = acc[i][4]; v1.y = acc[i][5]; v1.z = acc[i][6]; v1.w = acc[i][7];
        *(float4*)(g_conv + base)     = v0;
        *(float4*)(g_conv + base + 4) = v1;
    }
}

// ---------------------------------------------------------------------------
// Cumsum over k (W=12) in-place on g_conv
// ---------------------------------------------------------------------------
__global__ void cumsum_k() {
    int i = blockIdx.x * blockDim.x + threadIdx.x;   // over 2048*768
    if (i >= Mrows * Dc) return;
    int o = i % Dc;
    int m = i / Dc;
    float* p = g_conv + (size_t)m * Wc * Dc + o;
    float s = 0.f;
#pragma unroll
    for (int k = 0; k < Wc; k++) {
        s += p[(size_t)k * Dc];
        p[(size_t)k * Dc] = s;
    }
}

// ---------------------------------------------------------------------------
// GEMM 3 (gathered): out[m, d] = relu( sum_f relu(cat[m,f]) * out_w[d,f] + ob[d] )
//   M=24576, N=768, K=2304
//   cat[m, f]: f<768  -> g_proj[(b*512+sidx)*1536 + f]
//              f<1536 -> g_proj[(b*512+eidx)*1536 + 768 + (f-768)]
//              else   -> g_conv[m*768 + (f-1536)]
//   NOTE: span_idx arrives as int32 (JAX silently downgrades int64 without
//   x64 mode) — read as int pairs.
// ---------------------------------------------------------------------------
__global__ __launch_bounds__(NTHREADS)
void gemm_out(const int* __restrict__ span,
              const float* __restrict__ Wout,
              const float* __restrict__ bias,
              float* __restrict__ out) {
    __shared__ float As[BKK][BM];
    __shared__ float Bs[BKK][BN];
    const int K = Kout, N = Nout;
    int bm = blockIdx.y * BM, bn = blockIdx.x * BN;
    int t = threadIdx.x;
    int lr = t >> 1, lc4 = (t & 1) * 4;
    int ty = t >> 4, tx = t & 15;

    // per-thread gathered A row bases (constant over k-loop)
    int m = bm + lr;
    int b = m / (Lc * Wc);
    int si = span[(size_t)m * 2 + 0];
    int ei = span[(size_t)m * 2 + 1];
    si = si < 0 ? 0 : (si > Lc - 1 ? Lc - 1 : si);
    ei = ei < 0 ? 0 : (ei > Lc - 1 ? Lc - 1 : ei);
    const float* p0 = g_proj + (size_t)(b * Lc + si) * Nproj;
    const float* p1 = g_proj + (size_t)(b * Lc + ei) * Nproj + Dc;
    const float* p2 = g_conv + (size_t)m * Dc;
    const float* brow = Wout + (size_t)(bn + lr) * K;

    float acc[TM][TN];
#pragma unroll
    for (int i = 0; i < TM; i++)
#pragma unroll
        for (int j = 0; j < TN; j++) acc[i][j] = 0.f;

    for (int k0 = 0; k0 < K; k0 += BKK) {
        int f = k0 + lc4;
        const float* src;
        if (f < Dc)            src = p0 + f;
        else if (f < 2 * Dc)   src = p1 + (f - Dc);
        else                   src = p2 + (f - 2 * Dc);
        float4 av = *(const float4*)src;
        As[lc4 + 0][lr] = fmaxf(av.x, 0.f);
        As[lc4 + 1][lr] = fmaxf(av.y, 0.f);
        As[lc4 + 2][lr] = fmaxf(av.z, 0.f);
        As[lc4 + 3][lr] = fmaxf(av.w, 0.f);
        float4 bv = *(const float4*)(brow + k0 + lc4);
        Bs[lc4 + 0][lr] = bv.x; Bs[lc4 + 1][lr] = bv.y;
        Bs[lc4 + 2][lr] = bv.z; Bs[lc4 + 3][lr] = bv.w;
        __syncthreads();
#pragma unroll
        for (int kk = 0; kk < BKK; kk++) {
            float ar[TM], br[TN];
#pragma unroll
            for (int i = 0; i < TM; i++) ar[i] = As[kk][ty * TM + i];
#pragma unroll
            for (int j = 0; j < TN; j++) br[j] = Bs[kk][tx * TN + j];
#pragma unroll
            for (int i = 0; i < TM; i++)
#pragma unroll
                for (int j = 0; j < TN; j++) acc[i][j] += ar[i] * br[j];
        }
        __syncthreads();
    }

    float bvv[TN];
#pragma unroll
    for (int j = 0; j < TN; j++) bvv[j] = bias[bn + tx * TN + j];
#pragma unroll
    for (int i = 0; i < TM; i++) {
        int gm = bm + ty * TM + i;
        float4 v0, v1;
        v0.x = fmaxf(acc[i][0] + bvv[0], 0.f);
        v0.y = fmaxf(acc[i][1] + bvv[1], 0.f);
        v0.z = fmaxf(acc[i][2] + bvv[2], 0.f);
        v0.w = fmaxf(acc[i][3] + bvv[3], 0.f);
        v1.x = fmaxf(acc[i][4] + bvv[4], 0.f);
        v1.y = fmaxf(acc[i][5] + bvv[5], 0.f);
        v1.z = fmaxf(acc[i][6] + bvv[6], 0.f);
        v1.w = fmaxf(acc[i][7] + bvv[7], 0.f);
        *(float4*)(out + (size_t)gm * N + bn + tx * TN)     = v0;
        *(float4*)(out + (size_t)gm * N + bn + tx * TN + 4) = v1;
    }
}

// ---------------------------------------------------------------------------
extern "C" void kernel_launch(void* const* d_in, const int* in_sizes, int n_in,
                              void* d_out, int out_size) {
    const float* h    = (const float*)d_in[0];
    const int*   span = (const int*)d_in[1];
    const float* pw   = (const float*)d_in[2];
    const float* pb   = (const float*)d_in[3];
    const float* cw   = (const float*)d_in[4];
    const float* ow   = (const float*)d_in[5];
    const float* ob   = (const float*)d_in[6];
    float* out = (float*)d_out;
    (void)in_sizes; (void)n_in; (void)out_size;

    pack_convw<<<(Wc * Dc * Dc + 255) / 256, 256>>>(cw);
    gemm_proj<<<dim3(Nproj / BN, Mrows / BM), NTHREADS>>>(h, pw, pb);
    gemm_conv<<<dim3(Dc / BN, Mrows / BM, Wc), NTHREADS>>>(h);
    cumsum_k<<<(Mrows * Dc + 255) / 256, 256>>>();
    gemm_out<<<dim3(Nout / BN, Mout / BM), NTHREADS>>>(span, ow, ob, out);
}

// round 15
// speedup vs baseline: 1.0009x; 1.0009x over previous
#include <cuda_runtime.h>

// Problem constants
#define Bc 4
#define Lc 512
#define Dc 768
#define Wc 12
#define Mrows   (Bc * Lc)          // 2048
#define Mout    (Bc * Lc * Wc)     // 24576
#define Kproj   Dc                 // 768
#define Nproj   (2 * Dc)           // 1536
#define Kout    (3 * Dc)           // 2304
#define Nout    Dc                 // 768

// GEMM tiling
#define BM 128
#define BN 128
#define BKK 8
#define TM 8
#define TN 8
#define NTHREADS 256

// Scratch (device globals; allocation is forbidden)
__device__ float g_proj[Mrows * Nproj];          // 12.6 MB  [b*L+l][e]
__device__ float g_conv[(size_t)Mout * Dc];      // 75.5 MB  [((b*L+l)*W+k)][o]
__device__ float g_cw[Wc * Dc * Dc];             // 28.3 MB  [k][o][c]

// ---------------------------------------------------------------------------
// Pack conv_w (o, c, k) -> (k, o, c) for coalesced GEMM-B loads
// ---------------------------------------------------------------------------
__global__ void pack_convw(const float* __restrict__ cw) {
    int i = blockIdx.x * blockDim.x + threadIdx.x;
    if (i >= Wc * Dc * Dc) return;
    int c = i % Dc;
    int t = i / Dc;
    int o = t % Dc;
    int k = t / Dc;
    g_cw[i] = cw[(o * Dc + c) * Wc + k];
}

// ---------------------------------------------------------------------------
// GEMM 1: proj[m, e] = sum_d h[m, d] * proj_w[e, d] + proj_b[e]
//   M=2048, N=1536, K=768
// ---------------------------------------------------------------------------
__global__ __launch_bounds__(NTHREADS)
void gemm_proj(const float* __restrict__ A, const float* __restrict__ Bw,
               const float* __restrict__ bias) {
    __shared__ float As[BKK][BM];
    __shared__ float Bs[BKK][BN];
    const int K = Kproj, N = Nproj;
    int bm = blockIdx.y * BM, bn = blockIdx.x * BN;
    int t = threadIdx.x;
    int lr = t >> 1, lc4 = (t & 1) * 4;
    int ty = t >> 4, tx = t & 15;

    float acc[TM][TN];
#pragma unroll
    for (int i = 0; i < TM; i++)
#pragma unroll
        for (int j = 0; j < TN; j++) acc[i][j] = 0.f;

    for (int k0 = 0; k0 < K; k0 += BKK) {
        float4 av = *(const float4*)(A + (size_t)(bm + lr) * K + k0 + lc4);
        As[lc4 + 0][lr] = av.x; As[lc4 + 1][lr] = av.y;
        As[lc4 + 2][lr] = av.z; As[lc4 + 3][lr] = av.w;
        float4 bv = *(const float4*)(Bw + (size_t)(bn + lr) * K + k0 + lc4);
        Bs[lc4 + 0][lr] = bv.x; Bs[lc4 + 1][lr] = bv.y;
        Bs[lc4 + 2][lr] = bv.z; Bs[lc4 + 3][lr] = bv.w;
        __syncthreads();
#pragma unroll
        for (int kk = 0; kk < BKK; kk++) {
            float ar[TM], br[TN];
#pragma unroll
            for (int i = 0; i < TM; i++) ar[i] = As[kk][ty * TM + i];
#pragma unroll
            for (int j = 0; j < TN; j++) br[j] = Bs[kk][tx * TN + j];
#pragma unroll
            for (int i = 0; i < TM; i++)
#pragma unroll
                for (int j = 0; j < TN; j++) acc[i][j] += ar[i] * br[j];
        }
        __syncthreads();
    }

    float bvv[TN];
#pragma unroll
    for (int j = 0; j < TN; j++) bvv[j] = bias[bn + tx * TN + j];
#pragma unroll
    for (int i = 0; i < TM; i++) {
        int gm = bm + ty * TM + i;
        float4 v0, v1;
        v0.x = acc[i][0] + bvv[0]; v0.y = acc[i][1] + bvv[1];
        v0.z = acc[i][2] + bvv[2]; v0.w = acc[i][3] + bvv[3];
        v1.x = acc[i][4] + bvv[4]; v1.y = acc[i][5] + bvv[5];
        v1.z = acc[i][6] + bvv[6]; v1.w = acc[i][7] + bvv[7];
        *(float4*)(g_proj + (size_t)gm * N + bn + tx * TN)     = v0;
        *(float4*)(g_proj + (size_t)gm * N + bn + tx * TN + 4) = v1;
    }
}

// ---------------------------------------------------------------------------
// GEMM 2: P[m, o; k] = sum_c h[b, l+k, c] * g_cw[k][o][c]   (0 if l+k >= L)
//   grid.z = k. M=2048, N=768, K=768. Output indexed [m*W + k][o].
// ---------------------------------------------------------------------------
__global__ __launch_bounds__(NTHREADS)
void gemm_conv(const float* __restrict__ h) {
    __shared__ float As[BKK][BM];
    __shared__ float Bs[BKK][BN];
    const int K = Dc, N = Dc;
    int kz = blockIdx.z;
    int bm = blockIdx.y * BM, bn = blockIdx.x * BN;
    int t = threadIdx.x;
    int lr = t >> 1, lc4 = (t & 1) * 4;
    int ty = t >> 4, tx = t & 15;

    // per-thread A row (constant over k-loop)
    int m = bm + lr;
    int b = m >> 9;           // /512
    int l = m & 511;
    int ls = l + kz;
    const float* arow = (ls < Lc) ? (h + ((size_t)(b * Lc + ls)) * Dc) : nullptr;
    const float* brow = g_cw + (size_t)kz * Dc * Dc + (size_t)(bn + lr) * K;

    float acc[TM][TN];
#pragma unroll
    for (int i = 0; i < TM; i++)
#pragma unroll
        for (int j = 0; j < TN; j++) acc[i][j] = 0.f;

    for (int k0 = 0; k0 < K; k0 += BKK) {
        float4 av = make_float4(0.f, 0.f, 0.f, 0.f);
        if (arow) av = *(const float4*)(arow + k0 + lc4);
        As[lc4 + 0][lr] = av.x; As[lc4 + 1][lr] = av.y;
        As[lc4 + 2][lr] = av.z; As[lc4 + 3][lr] = av.w;
        float4 bv = *(const float4*)(brow + k0 + lc4);
        Bs[lc4 + 0][lr] = bv.x; Bs[lc4 + 1][lr] = bv.y;
        Bs[lc4 + 2][lr] = bv.z; Bs[lc4 + 3][lr] = bv.w;
        __syncthreads();
#pragma unroll
        for (int kk = 0; kk < BKK; kk++) {
            float ar[TM], br[TN];
#pragma unroll
            for (int i = 0; i < TM; i++) ar[i] = As[kk][ty * TM + i];
#pragma unroll
            for (int j = 0; j < TN; j++) br[j] = Bs[kk][tx * TN + j];
#pragma unroll
            for (int i = 0; i < TM; i++)
#pragma unroll
                for (int j = 0; j < TN; j++) acc[i][j] += ar[i] * br[j];
        }
        __syncthreads();
    }

#pragma unroll
    for (int i = 0; i < TM; i++) {
        int gm = bm + ty * TM + i;
        size_t base = ((size_t)gm * Wc + kz) * (size_t)N + bn + tx * TN;
        float4 v0, v1;
        v0.x = acc[i][0]; v0.y = acc[i][1]; v0.z = acc[i][2]; v0.w = acc[i][3];
        v1.x = acc[i][4]; v1.y = acc[i][5]; v1.z = acc[i][6]; v1.w = acc[i][7];
        *(float4*)(g_conv + base)     = v0;
        *(float4*)(g_conv + base + 4) = v1;
    }
}

// ---------------------------------------------------------------------------
// Cumsum over k (W=12) in-place on g_conv
// ---------------------------------------------------------------------------
__global__ void cumsum_k() {
    int i = blockIdx.x * blockDim.x + threadIdx.x;   // over 2048*768
    if (i >= Mrows * Dc) return;
    int o = i % Dc;
    int m = i / Dc;
    float* p = g_conv + (size_t)m * Wc * Dc + o;
    float s = 0.f;
#pragma unroll
    for (int k = 0; k < Wc; k++) {
        s += p[(size_t)k * Dc];
        p[(size_t)k * Dc] = s;
    }
}

// ---------------------------------------------------------------------------
// GEMM 3 (gathered): out[m, d] = relu( sum_f relu(cat[m,f]) * out_w[d,f] + ob[d] )
//   M=24576, N=768, K=2304
//   cat[m, f]: f<768  -> g_proj[(b*512+sidx)*1536 + f]
//              f<1536 -> g_proj[(b*512+eidx)*1536 + 768 + (f-768)]
//              else   -> g_conv[m*768 + (f-1536)]
//   NOTE: span_idx arrives as int32 (JAX silently downgrades int64 without
//   x64 mode) — read as int pairs.
// ---------------------------------------------------------------------------
__global__ __launch_bounds__(NTHREADS)
void gemm_out(const int* __restrict__ span,
              const float* __restrict__ Wout,
              const float* __restrict__ bias,
              float* __restrict__ out) {
    __shared__ float As[BKK][BM];
    __shared__ float Bs[BKK][BN];
    const int K = Kout, N = Nout;
    int bm = blockIdx.y * BM, bn = blockIdx.x * BN;
    int t = threadIdx.x;
    int lr = t >> 1, lc4 = (t & 1) * 4;
    int ty = t >> 4, tx = t & 15;

    // per-thread gathered A row bases (constant over k-loop)
    int m = bm + lr;
    int b = m / (Lc * Wc);
    int si = span[(size_t)m * 2 + 0];
    int ei = span[(size_t)m * 2 + 1];
    si = si < 0 ? 0 : (si > Lc - 1 ? Lc - 1 : si);
    ei = ei < 0 ? 0 : (ei > Lc - 1 ? Lc - 1 : ei);
    const float* p0 = g_proj + (size_t)(b * Lc + si) * Nproj;
    const float* p1 = g_proj + (size_t)(b * Lc + ei) * Nproj + Dc;
    const float* p2 = g_conv + (size_t)m * Dc;
    const float* brow = Wout + (size_t)(bn + lr) * K;

    float acc[TM][TN];
#pragma unroll
    for (int i = 0; i < TM; i++)
#pragma unroll
        for (int j = 0; j < TN; j++) acc[i][j] = 0.f;

    for (int k0 = 0; k0 < K; k0 += BKK) {
        int f = k0 + lc4;
        const float* src;
        if (f < Dc)            src = p0 + f;
        else if (f < 2 * Dc)   src = p1 + (f - Dc);
        else                   src = p2 + (f - 2 * Dc);
        float4 av = *(const float4*)src;
        As[lc4 + 0][lr] = fmaxf(av.x, 0.f);
        As[lc4 + 1][lr] = fmaxf(av.y, 0.f);
        As[lc4 + 2][lr] = fmaxf(av.z, 0.f);
        As[lc4 + 3][lr] = fmaxf(av.w, 0.f);
        float4 bv = *(const float4*)(brow + k0 + lc4);
        Bs[lc4 + 0][lr] = bv.x; Bs[lc4 + 1][lr] = bv.y;
        Bs[lc4 + 2][lr] = bv.z; Bs[lc4 + 3][lr] = bv.w;
        __syncthreads();
#pragma unroll
        for (int kk = 0; kk < BKK; kk++) {
            float ar[TM], br[TN];
#pragma unroll
            for (int i = 0; i < TM; i++) ar[i] = As[kk][ty * TM + i];
#pragma unroll
            for (int j = 0; j < TN; j++) br[j] = Bs[kk][tx * TN + j];
#pragma unroll
            for (int i = 0; i < TM; i++)
#pragma unroll
                for (int j = 0; j < TN; j++) acc[i][j] += ar[i] * br[j];
        }
        __syncthreads();
    }

    float bvv[TN];
#pragma unroll
    for (int j = 0; j < TN; j++) bvv[j] = bias[bn + tx * TN + j];
#pragma unroll
    for (int i = 0; i < TM; i++) {
        int gm = bm + ty * TM + i;
        float4 v0, v1;
        v0.x = fmaxf(acc[i][0] + bvv[0], 0.f);
        v0.y = fmaxf(acc[i][1] + bvv[1], 0.f);
        v0.z = fmaxf(acc[i][2] + bvv[2], 0.f);
        v0.w = fmaxf(acc[i][3] + bvv[3], 0.f);
        v1.x = fmaxf(acc[i][4] + bvv[4], 0.f);
        v1.y = fmaxf(acc[i][5] + bvv[5], 0.f);
        v1.z = fmaxf(acc[i][6] + bvv[6], 0.f);
        v1.w = fmaxf(acc[i][7] + bvv[7], 0.f);
        *(float4*)(out + (size_t)gm * N + bn + tx * TN)     = v0;
        *(float4*)(out + (size_t)gm * N + bn + tx * TN + 4) = v1;
    }
}

// ---------------------------------------------------------------------------
extern "C" void kernel_launch(void* const* d_in, const int* in_sizes, int n_in,
                              void* d_out, int out_size) {
    const float* h    = (const float*)d_in[0];
    const int*   span = (const int*)d_in[1];
    const float* pw   = (const float*)d_in[2];
    const float* pb   = (const float*)d_in[3];
    const float* cw   = (const float*)d_in[4];
    const float* ow   = (const float*)d_in[5];
    const float* ob   = (const float*)d_in[6];
    float* out = (float*)d_out;
    (void)in_sizes; (void)n_in; (void)out_size;

    pack_convw<<<(Wc * Dc * Dc + 255) / 256, 256>>>(cw);
    gemm_proj<<<dim3(Nproj / BN, Mrows / BM), NTHREADS>>>(h, pw, pb);
    gemm_conv<<<dim3(Dc / BN, Mrows / BM, Wc), NTHREADS>>>(h);
    cumsum_k<<<(Mrows * Dc + 255) / 256, 256>>>();
    gemm_out<<<dim3(Nout / BN, Mout / BM), NTHREADS>>>(span, ow, ob, out);
}

// round 16
// speedup vs baseline: 2.6588x; 2.6564x over previous
#include <cuda_runtime.h>
#include <cstdint>

// Problem constants
#define Bc 4
#define Lc 512
#define Dc 768
#define Wc 12
#define Mrows   (Bc * Lc)          // 2048
#define Mout    (Bc * Lc * Wc)     // 24576
#define Nproj   (2 * Dc)           // 1536
#define Kout    (3 * Dc)           // 2304

// Tensor-core GEMM tiling: 128x128 CTA tile, BK=32, 8 warps (2M x 4N),
// warp tile 64x32 = 4x4 m16n8k8 fragments.
#define BM 128
#define BN 128
#define BK 32
#define NTH 256
#define SPAD 36   // smem row stride (floats): 32 + 4 pad -> conflict-free frags

// Scratch (device globals; allocation is forbidden)
__device__ float g_proj[Mrows * Nproj];          // 12.6 MB
__device__ float g_conv[(size_t)Mout * Dc];      // 75.5 MB
__device__ float g_cw[Wc * Dc * Dc];             // 28.3 MB [k][o][c]

// ---------------------------------------------------------------------------
__device__ __forceinline__ uint32_t f2tf(float x) {
    uint32_t r; asm("cvt.rna.tf32.f32 %0, %1;" : "=r"(r) : "f"(x)); return r;
}

__device__ __forceinline__ void mma8(float* d, const uint32_t* a, const uint32_t* b) {
    asm volatile(
        "mma.sync.aligned.m16n8k8.row.col.f32.tf32.tf32.f32 "
        "{%0,%1,%2,%3}, {%4,%5,%6,%7}, {%8,%9}, {%0,%1,%2,%3};"
        : "+f"(d[0]), "+f"(d[1]), "+f"(d[2]), "+f"(d[3])
        : "r"(a[0]), "r"(a[1]), "r"(a[2]), "r"(a[3]), "r"(b[0]), "r"(b[1]));
}

// Compute one BK=32 slab from smem.
__device__ __forceinline__ void mma_stage(
    const uint32_t As[BM][SPAD], const uint32_t Bs[BN][SPAD],
    float acc[4][4][4], int wm, int wn, int g, int tig)
{
#pragma unroll
    for (int ks = 0; ks < BK / 8; ks++) {
        uint32_t a[4][4], b[4][2];
#pragma unroll
        for (int mt = 0; mt < 4; mt++) {
            int r = wm + mt * 16 + g;
            a[mt][0] = As[r][ks * 8 + tig];
            a[mt][1] = As[r + 8][ks * 8 + tig];
            a[mt][2] = As[r][ks * 8 + tig + 4];
            a[mt][3] = As[r + 8][ks * 8 + tig + 4];
        }
#pragma unroll
        for (int nt = 0; nt < 4; nt++) {
            int c = wn + nt * 8 + g;
            b[nt][0] = Bs[c][ks * 8 + tig];
            b[nt][1] = Bs[c][ks * 8 + tig + 4];
        }
#pragma unroll
        for (int mt = 0; mt < 4; mt++)
#pragma unroll
            for (int nt = 0; nt < 4; nt++)
                mma8(acc[mt][nt], a[mt], b[nt]);
    }
}

#define ZERO_ACC(acc)                                   \
    _Pragma("unroll") for (int _i = 0; _i < 4; _i++)    \
    _Pragma("unroll") for (int _j = 0; _j < 4; _j++)    \
    _Pragma("unroll") for (int _k = 0; _k < 4; _k++) acc[_i][_j][_k] = 0.f;

#define STORE_SLAB(As, Bs, ap, bp, lrow, lcol)          \
    _Pragma("unroll") for (int _i = 0; _i < 4; _i++) {  \
        As[lrow + 32 * _i][lcol + 0] = f2tf(ap[_i].x);  \
        As[lrow + 32 * _i][lcol + 1] = f2tf(ap[_i].y);  \
        As[lrow + 32 * _i][lcol + 2] = f2tf(ap[_i].z);  \
        As[lrow + 32 * _i][lcol + 3] = f2tf(ap[_i].w);  \
        Bs[lrow + 32 * _i][lcol + 0] = f2tf(bp[_i].x);  \
        Bs[lrow + 32 * _i][lcol + 1] = f2tf(bp[_i].y);  \
        Bs[lrow + 32 * _i][lcol + 2] = f2tf(bp[_i].z);  \
        Bs[lrow + 32 * _i][lcol + 3] = f2tf(bp[_i].w);  \
    }

// ---------------------------------------------------------------------------
// Pack conv_w (o, c, k) -> (k, o, c)
// ---------------------------------------------------------------------------
__global__ void pack_convw(const float* __restrict__ cw) {
    int i = blockIdx.x * blockDim.x + threadIdx.x;
    if (i >= Wc * Dc * Dc) return;
    int c = i % Dc;
    int t = i / Dc;
    int o = t % Dc;
    int k = t / Dc;
    g_cw[i] = cw[(o * Dc + c) * Wc + k];
}

// ---------------------------------------------------------------------------
// GEMM 1 (tf32): proj = h @ proj_w^T + proj_b.  M=2048, N=1536, K=768
// ---------------------------------------------------------------------------
__global__ __launch_bounds__(NTH)
void gemm_proj(const float* __restrict__ A, const float* __restrict__ Bw,
               const float* __restrict__ bias) {
    __shared__ uint32_t As[BM][SPAD], Bs[BN][SPAD];
    const int K = Dc, N = Nproj;
    int bm = blockIdx.y * BM, bn = blockIdx.x * BN;
    int tid = threadIdx.x;
    int lrow = tid >> 3, lcol = (tid & 7) * 4;
    int warp = tid >> 5, lane = tid & 31, g = lane >> 2, tig = lane & 3;
    int wm = (warp & 1) * 64, wn = (warp >> 1) * 32;

    float acc[4][4][4];
    ZERO_ACC(acc);

    const float* a0 = A + (size_t)(bm + lrow) * K + lcol;
    const float* b0 = Bw + (size_t)(bn + lrow) * K + lcol;

    float4 ap[4], bp[4];
#pragma unroll
    for (int i = 0; i < 4; i++) {
        ap[i] = *(const float4*)(a0 + (size_t)(32 * i) * K);
        bp[i] = *(const float4*)(b0 + (size_t)(32 * i) * K);
    }
    STORE_SLAB(As, Bs, ap, bp, lrow, lcol);
    __syncthreads();

    for (int k0 = 0; k0 < K; k0 += BK) {
        bool more = (k0 + BK < K);
        if (more) {
#pragma unroll
            for (int i = 0; i < 4; i++) {
                ap[i] = *(const float4*)(a0 + (size_t)(32 * i) * K + k0 + BK);
                bp[i] = *(const float4*)(b0 + (size_t)(32 * i) * K + k0 + BK);
            }
        }
        mma_stage(As, Bs, acc, wm, wn, g, tig);
        __syncthreads();
        if (more) {
            STORE_SLAB(As, Bs, ap, bp, lrow, lcol);
            __syncthreads();
        }
    }

#pragma unroll
    for (int mt = 0; mt < 4; mt++)
#pragma unroll
        for (int nt = 0; nt < 4; nt++) {
            int r0 = bm + wm + mt * 16 + g;
            int c0 = bn + wn + nt * 8 + 2 * tig;
            float bb0 = bias[c0], bb1 = bias[c0 + 1];
            float2 v;
            v.x = acc[mt][nt][0] + bb0; v.y = acc[mt][nt][1] + bb1;
            *(float2*)(g_proj + (size_t)r0 * N + c0) = v;
            v.x = acc[mt][nt][2] + bb0; v.y = acc[mt][nt][3] + bb1;
            *(float2*)(g_proj + (size_t)(r0 + 8) * N + c0) = v;
        }
}

// ---------------------------------------------------------------------------
// GEMM 2 (tf32): contrib[m, o; kz] = h[b, l+kz] @ g_cw[kz]^T  (0 beyond L)
//   grid.z = kz. M=2048, N=768, K=768. Output [m*W + kz][o].
// ---------------------------------------------------------------------------
__global__ __launch_bounds__(NTH)
void gemm_conv(const float* __restrict__ h) {
    __shared__ uint32_t As[BM][SPAD], Bs[BN][SPAD];
    const int K = Dc, N = Dc;
    int kz = blockIdx.z;
    int bm = blockIdx.y * BM, bn = blockIdx.x * BN;
    int tid = threadIdx.x;
    int lrow = tid >> 3, lcol = (tid & 7) * 4;
    int warp = tid >> 5, lane = tid & 31, g = lane >> 2, tig = lane & 3;
    int wm = (warp & 1) * 64, wn = (warp >> 1) * 32;

    float acc[4][4][4];
    ZERO_ACC(acc);

    const float* arow[4];
#pragma unroll
    for (int i = 0; i < 4; i++) {
        int m = bm + lrow + 32 * i;
        int b = m >> 9;
        int l = m & 511;
        int ls = l + kz;
        arow[i] = (ls < Lc) ? (h + (size_t)(b * Lc + ls) * Dc + lcol) : nullptr;
    }
    const float* b0 = g_cw + (size_t)kz * Dc * Dc + (size_t)(bn + lrow) * K + lcol;

    float4 ap[4], bp[4];
#pragma unroll
    for (int i = 0; i < 4; i++) {
        ap[i] = arow[i] ? *(const float4*)(arow[i]) : make_float4(0.f, 0.f, 0.f, 0.f);
        bp[i] = *(const float4*)(b0 + (size_t)(32 * i) * K);
    }
    STORE_SLAB(As, Bs, ap, bp, lrow, lcol);
    __syncthreads();

    for (int k0 = 0; k0 < K; k0 += BK) {
        bool more = (k0 + BK < K);
        if (more) {
#pragma unroll
            for (int i = 0; i < 4; i++) {
                ap[i] = arow[i] ? *(const float4*)(arow[i] + k0 + BK)
                                : make_float4(0.f, 0.f, 0.f, 0.f);
                bp[i] = *(const float4*)(b0 + (size_t)(32 * i) * K + k0 + BK);
            }
        }
        mma_stage(As, Bs, acc, wm, wn, g, tig);
        __syncthreads();
        if (more) {
            STORE_SLAB(As, Bs, ap, bp, lrow, lcol);
            __syncthreads();
        }
    }

#pragma unroll
    for (int mt = 0; mt < 4; mt++)
#pragma unroll
        for (int nt = 0; nt < 4; nt++) {
            int r0 = bm + wm + mt * 16 + g;
            int c0 = bn + wn + nt * 8 + 2 * tig;
            size_t base0 = ((size_t)r0 * Wc + kz) * (size_t)N + c0;
            size_t base1 = ((size_t)(r0 + 8) * Wc + kz) * (size_t)N + c0;
            float2 v;
            v.x = acc[mt][nt][0]; v.y = acc[mt][nt][1];
            *(float2*)(g_conv + base0) = v;
            v.x = acc[mt][nt][2]; v.y = acc[mt][nt][3];
            *(float2*)(g_conv + base1) = v;
        }
}

// ---------------------------------------------------------------------------
// Cumsum over k (W=12) in-place on g_conv, float4-vectorized
// ---------------------------------------------------------------------------
__global__ void cumsum_k() {
    int i = blockIdx.x * blockDim.x + threadIdx.x;   // over 2048 * 192
    if (i >= Mrows * (Dc / 4)) return;
    int o4 = i % (Dc / 4);
    int m = i / (Dc / 4);
    float* p = g_conv + (size_t)m * Wc * Dc + o4 * 4;
    float4 s = make_float4(0.f, 0.f, 0.f, 0.f);
#pragma unroll
    for (int k = 0; k < Wc; k++) {
        float4 v = *(float4*)(p + (size_t)k * Dc);
        s.x += v.x; s.y += v.y; s.z += v.z; s.w += v.w;
        *(float4*)(p + (size_t)k * Dc) = s;
    }
}

// ---------------------------------------------------------------------------
// GEMM 3 (tf32, gathered): out = relu(relu(cat) @ out_w^T + ob)
//   M=24576, N=768, K=2304. span_idx is int32 (JAX x64 off).
// ---------------------------------------------------------------------------
__global__ __launch_bounds__(NTH)
void gemm_out(const int* __restrict__ span,
              const float* __restrict__ Wout,
              const float* __restrict__ bias,
              float* __restrict__ out) {
    __shared__ uint32_t As[BM][SPAD], Bs[BN][SPAD];
    const int K = Kout, N = Dc;
    int bm = blockIdx.y * BM, bn = blockIdx.x * BN;
    int tid = threadIdx.x;
    int lrow = tid >> 3, lcol = (tid & 7) * 4;
    int warp = tid >> 5, lane = tid & 31, g = lane >> 2, tig = lane & 3;
    int wm = (warp & 1) * 64, wn = (warp >> 1) * 32;

    float acc[4][4][4];
    ZERO_ACC(acc);

    // Per-row gathered segment bases (a BK=32 slab never straddles the
    // 768/1536 boundaries since 768 % 32 == 0).
    const float* base0[4];
    const float* base1[4];
    const float* base2[4];
#pragma unroll
    for (int i = 0; i < 4; i++) {
        int m = bm + lrow + 32 * i;
        int b = m / (Lc * Wc);
        int si = span[(size_t)m * 2 + 0];
        int ei = span[(size_t)m * 2 + 1];
        si = si < 0 ? 0 : (si > Lc - 1 ? Lc - 1 : si);
        ei = ei < 0 ? 0 : (ei > Lc - 1 ? Lc - 1 : ei);
        base0[i] = g_proj + (size_t)(b * Lc + si) * Nproj + lcol;
        base1[i] = g_proj + (size_t)(b * Lc + ei) * Nproj + Dc + lcol;
        base2[i] = g_conv + (size_t)m * Dc + lcol;
    }
    const float* b0 = Wout + (size_t)(bn + lrow) * K + lcol;

    float4 ap[4], bp[4];

#define LOAD_OUT_SLAB(k0)                                                    \
    {                                                                        \
        _Pragma("unroll") for (int i = 0; i < 4; i++) {                      \
            const float* src;                                                \
            if ((k0) < Dc)            src = base0[i] + (k0);                 \
            else if ((k0) < 2 * Dc)   src = base1[i] + ((k0) - Dc);          \
            else                      src = base2[i] + ((k0) - 2 * Dc);      \
            float4 av = *(const float4*)src;                                 \
            ap[i].x = fmaxf(av.x, 0.f); ap[i].y = fmaxf(av.y, 0.f);          \
            ap[i].z = fmaxf(av.z, 0.f); ap[i].w = fmaxf(av.w, 0.f);          \
            bp[i] = *(const float4*)(b0 + (size_t)(32 * i) * K + (k0));      \
        }                                                                    \
    }

    LOAD_OUT_SLAB(0);
    STORE_SLAB(As, Bs, ap, bp, lrow, lcol);
    __syncthreads();

    for (int k0 = 0; k0 < K; k0 += BK) {
        bool more = (k0 + BK < K);
        if (more) LOAD_OUT_SLAB(k0 + BK);
        mma_stage(As, Bs, acc, wm, wn, g, tig);
        __syncthreads();
        if (more) {
            STORE_SLAB(As, Bs, ap, bp, lrow, lcol);
            __syncthreads();
        }
    }

#pragma unroll
    for (int mt = 0; mt < 4; mt++)
#pragma unroll
        for (int nt = 0; nt < 4; nt++) {
            int r0 = bm + wm + mt * 16 + g;
            int c0 = bn + wn + nt * 8 + 2 * tig;
            float bb0 = bias[c0], bb1 = bias[c0 + 1];
            float2 v;
            v.x = fmaxf(acc[mt][nt][0] + bb0, 0.f);
            v.y = fmaxf(acc[mt][nt][1] + bb1, 0.f);
            *(float2*)(out + (size_t)r0 * N + c0) = v;
            v.x = fmaxf(acc[mt][nt][2] + bb0, 0.f);
            v.y = fmaxf(acc[mt][nt][3] + bb1, 0.f);
            *(float2*)(out + (size_t)(r0 + 8) * N + c0) = v;
        }
}

// ---------------------------------------------------------------------------
extern "C" void kernel_launch(void* const* d_in, const int* in_sizes, int n_in,
                              void* d_out, int out_size) {
    const float* h    = (const float*)d_in[0];
    const int*   span = (const int*)d_in[1];
    const float* pw   = (const float*)d_in[2];
    const float* pb   = (const float*)d_in[3];
    const float* cw   = (const float*)d_in[4];
    const float* ow   = (const float*)d_in[5];
    const float* ob   = (const float*)d_in[6];
    float* out = (float*)d_out;
    (void)in_sizes; (void)n_in; (void)out_size;

    pack_convw<<<(Wc * Dc * Dc + 255) / 256, 256>>>(cw);
    gemm_proj<<<dim3(Nproj / BN, Mrows / BM), NTH>>>(h, pw, pb);
    gemm_conv<<<dim3(Dc / BN, Mrows / BM, Wc), NTH>>>(h);
    cumsum_k<<<(Mrows * (Dc / 4) + 255) / 256, 256>>>();
    gemm_out<<<dim3(Dc / BN, Mout / BM), NTH>>>(span, ow, ob, out);
}